// round 17
// baseline (speedup 1.0000x reference)
#include <cuda_runtime.h>
#include <cstdint>

#define D 128
#define C 32
#define LSEQ 4096
#define BH 32
#define NCHUNK 128              // chunks per (b,h)
#define NC_TOTAL 4096           // total chunks
#define ASTR 36                 // 32x32 matrix row stride (pad 4, 16B-aligned rows)
#define RSTR 132                // 32x128 chunk row stride (pad 4, keeps 16B align)
#define KTSTR 36                // kT tile row stride (128 rows x 32 cols, pad 4)
#define VSLICE 32               // dv slice width per scan CTA
#define NSPLIT 4                // dv splits

// Scratch (allocation-free rule: __device__ globals)
// g_kn holds k TRANSPOSED per chunk: [chunk][d 0..127][row 0..31]
__device__ float g_kn[BH * LSEQ * D];
__device__ float g_w [BH * LSEQ * D];
__device__ float g_u [BH * LSEQ * D];
__device__ float g_attn[NC_TOTAL * C * C];
__device__ float g_qr[NC_TOTAL * C];     // per-row q normalization scale

// ---------------- packed f32x2 helpers (FFMA2 path, sm_100+) ----------------
__device__ __forceinline__ unsigned long long pk2(float v) {
    unsigned long long r;
    asm("mov.b64 %0, {%1, %1};" : "=l"(r) : "f"(v));
    return r;
}
__device__ __forceinline__ unsigned long long pkf(float lo, float hi) {
    unsigned long long r;
    asm("mov.b64 %0, {%1, %2};" : "=l"(r) : "f"(lo), "f"(hi));
    return r;
}
__device__ __forceinline__ void fma2(unsigned long long& a,
                                     unsigned long long b, unsigned long long c) {
    asm("fma.rn.f32x2 %0, %1, %2, %0;" : "+l"(a) : "l"(b), "l"(c));
}
__device__ __forceinline__ float2 up2(unsigned long long a) {
    float2 f;
    asm("mov.b64 {%0, %1}, %2;" : "=f"(f.x), "=f"(f.y) : "l"(a));
    return f;
}
__device__ __forceinline__ float hadd2(unsigned long long a) {
    float2 f = up2(a); return f.x + f.y;
}
__device__ __forceinline__ void cpa16(uint32_t s, const float* g) {
    asm volatile("cp.async.cg.shared.global [%0], [%1], 16;" :: "r"(s), "l"(g));
}

// ---------------------------------------------------------------------------
// Kernel A: per-chunk preprocessing.
// R16 logic minus the g_qn store (scan normalizes q on the fly via g_qr);
// phase-2 unroll reduced to relieve register pressure at 3 CTAs/SM.
// ---------------------------------------------------------------------------
__global__ void __launch_bounds__(256, 3) prep_kernel(
    const float* __restrict__ q, const float* __restrict__ k,
    const float* __restrict__ v, const float* __restrict__ beta)
{
    extern __shared__ float s[];
    float* sqn = s;                       // 32 x RSTR
    float* skn = sqn + C * RSTR;          // 32 x 128 (XOR-swizzled chunks)
    float* skb = skn + C * 128;           // 32 x RSTR
    float* sv  = skb + C * RSTR;          // 32 x RSTR
    float* sA  = sv  + C * RSTR;          // 32 x ASTR
    float* sP  = sA  + C * ASTR;          // 16 x 17 Schur temp

    const int nc  = blockIdx.x;
    const int t   = threadIdx.x;
    const int w   = t >> 5;
    const int lid = t & 31;
    const size_t base = (size_t)nc * (C * D);

    // ---- Phase 1: normalize + scale ----
    #pragma unroll
    for (int rr = 0; rr < 4; rr++) {
        const int r = w * 4 + rr;
        const float bet = __ldg(beta + (size_t)nc * C + r);
        float4 q4 = *(const float4*)(q + base + r * D + lid * 4);
        float4 k4 = *(const float4*)(k + base + r * D + lid * 4);
        float4 v4 = *(const float4*)(v + base + r * D + lid * 4);
        float qs = q4.x*q4.x + q4.y*q4.y + q4.z*q4.z + q4.w*q4.w;
        float ks = k4.x*k4.x + k4.y*k4.y + k4.z*k4.z + k4.w*k4.w;
        #pragma unroll
        for (int o = 16; o > 0; o >>= 1) {
            qs += __shfl_xor_sync(0xffffffffu, qs, o);
            ks += __shfl_xor_sync(0xffffffffu, ks, o);
        }
        const float qr = rsqrtf(qs + 1e-6f);
        const float kr = rsqrtf(ks + 1e-6f);
        float4 qn = make_float4(q4.x*qr, q4.y*qr, q4.z*qr, q4.w*qr);
        float4 kn = make_float4(k4.x*kr, k4.y*kr, k4.z*kr, k4.w*kr);
        float4 kb = make_float4(kn.x*bet, kn.y*bet, kn.z*bet, kn.w*bet);
        float4 vb = make_float4(v4.x*bet, v4.y*bet, v4.z*bet, v4.w*bet);
        *(float4*)(sqn + r * RSTR + lid * 4) = qn;
        *(float4*)(skn + r * 128 + ((lid ^ (r & 7)) << 2)) = kn;
        *(float4*)(skb + r * RSTR + lid * 4) = kb;
        *(float4*)(sv  + r * RSTR + lid * 4) = vb;
        if (lid == 0) g_qr[(size_t)nc * C + r] = qr;   // scan rescales raw q
    }
    __syncthreads();

    // ---- Phase 2: A (strict-lower, negated) and attn (lower incl diag) ----
    {
        const int j  = lid;
        const int i0 = w * 4;
        const int jx = (j & 7);
        unsigned long long A0=0,A1=0,A2=0,A3=0,T0=0,T1=0,T2=0,T3=0;
        const float* kjp = skn + j * 128;
        const float* b0p = skb + (i0+0) * RSTR;
        const float* b1p = skb + (i0+1) * RSTR;
        const float* b2p = skb + (i0+2) * RSTR;
        const float* b3p = skb + (i0+3) * RSTR;
        const float* q0p = sqn + (i0+0) * RSTR;
        const float* q1p = sqn + (i0+1) * RSTR;
        const float* q2p = sqn + (i0+2) * RSTR;
        const float* q3p = sqn + (i0+3) * RSTR;
        #pragma unroll 2
        for (int d = 0; d < D; d += 4) {
            ulonglong2 kj = *(const ulonglong2*)(kjp + ((((d >> 2) ^ jx)) << 2));
            ulonglong2 b0 = *(const ulonglong2*)(b0p + d);
            ulonglong2 b1 = *(const ulonglong2*)(b1p + d);
            ulonglong2 b2 = *(const ulonglong2*)(b2p + d);
            ulonglong2 b3 = *(const ulonglong2*)(b3p + d);
            fma2(A0, b0.x, kj.x); fma2(A0, b0.y, kj.y);
            fma2(A1, b1.x, kj.x); fma2(A1, b1.y, kj.y);
            fma2(A2, b2.x, kj.x); fma2(A2, b2.y, kj.y);
            fma2(A3, b3.x, kj.x); fma2(A3, b3.y, kj.y);
            ulonglong2 c0 = *(const ulonglong2*)(q0p + d);
            ulonglong2 c1 = *(const ulonglong2*)(q1p + d);
            ulonglong2 c2 = *(const ulonglong2*)(q2p + d);
            ulonglong2 c3 = *(const ulonglong2*)(q3p + d);
            fma2(T0, c0.x, kj.x); fma2(T0, c0.y, kj.y);
            fma2(T1, c1.x, kj.x); fma2(T1, c1.y, kj.y);
            fma2(T2, c2.x, kj.x); fma2(T2, c2.y, kj.y);
            fma2(T3, c3.x, kj.x); fma2(T3, c3.y, kj.y);
        }
        const float a0 = hadd2(A0), a1 = hadd2(A1), a2 = hadd2(A2), a3 = hadd2(A3);
        const float t0 = hadd2(T0), t1 = hadd2(T1), t2 = hadd2(T2), t3 = hadd2(T3);
        float* ga = g_attn + (size_t)nc * (C * C);
        sA[(i0+0)*ASTR + j] = (j < i0+0) ? -a0 : 0.f;
        sA[(i0+1)*ASTR + j] = (j < i0+1) ? -a1 : 0.f;
        sA[(i0+2)*ASTR + j] = (j < i0+2) ? -a2 : 0.f;
        sA[(i0+3)*ASTR + j] = (j < i0+3) ? -a3 : 0.f;
        ga[(i0+0)*C + j] = (j <= i0+0) ? t0 : 0.f;
        ga[(i0+1)*C + j] = (j <= i0+1) ? t1 : 0.f;
        ga[(i0+2)*C + j] = (j <= i0+2) ? t2 : 0.f;
        ga[(i0+3)*C + j] = (j <= i0+3) ? t3 : 0.f;
    }
    __syncthreads();

    // ---- Phase 3a (warps 0-1) || kT transpose store (warps 2-7) ----
    if (w < 2) {
        const int b0 = w * 16;
        const int j  = lid & 15;
        for (int i = 1; i < 16; i++) {
            float acc = 0.f;
            for (int kk = j + 1; kk < i; kk++)
                acc += sA[(b0+i)*ASTR + b0+kk] * sA[(b0+kk)*ASTR + b0+j];
            __syncwarp();
            if (lid < 16 && j < i) sA[(b0+i)*ASTR + b0+j] += acc;
            __syncwarp();
        }
        if (lid < 16) sA[(b0+j)*ASTR + b0+j] = 1.0f;
    } else {
        // g_kn[chunk][d][r] = kn[r][d] (coalesced STG); 192 threads, 256 slots
        for (int idx = t - 64; idx < 256; idx += 192) {
            const int r4 = (idx & 7) * 4;
            const int d0 = idx >> 3;            // 0..31
            #pragma unroll
            for (int i = 0; i < 4; i++) {
                const int d = d0 + 32 * i;
                const int g = d >> 2, lo = d & 3;
                float4 kk;
                kk.x = skn[(r4+0) * 128 + ((g ^ ((r4+0) & 7)) << 2) + lo];
                kk.y = skn[(r4+1) * 128 + ((g ^ ((r4+1) & 7)) << 2) + lo];
                kk.z = skn[(r4+2) * 128 + ((g ^ ((r4+2) & 7)) << 2) + lo];
                kk.w = skn[(r4+3) * 128 + ((g ^ ((r4+3) & 7)) << 2) + lo];
                *(float4*)(g_kn + base + d * C + r4) = kk;
            }
        }
    }
    __syncthreads();

    // ---- Phase 3b: Schur combine  X21 = X22 * A21 * X11 ----
    {
        const int r = t >> 4;
        const int cc = t & 15;
        float acc = 0.f;
        #pragma unroll 4
        for (int e = 0; e < 16; e++)
            acc += sA[(16+r)*ASTR + e] * sA[e*ASTR + cc];
        sP[r * 17 + cc] = acc;
        __syncthreads();
        float acc2 = 0.f;
        #pragma unroll 4
        for (int e = 0; e < 16; e++)
            acc2 += sA[(16+r)*ASTR + 16+e] * sP[e * 17 + cc];
        sA[(16+r)*ASTR + cc] = acc2;
    }
    __syncthreads();

    // ---- Phase 4: u = inv@v , w = inv@kb ----
    {
        const int i  = t >> 3;
        const int dl = (t & 7) * 4;
        #pragma unroll
        for (int db = 0; db < 4; db++) {
            const int d = db * 32 + dl;
            unsigned long long au01=0, au23=0, aw01=0, aw23=0;
            #pragma unroll 4
            for (int j0 = 0; j0 < C; j0 += 4) {
                float4 a4 = *(const float4*)(sA + i*ASTR + j0);
                #pragma unroll
                for (int jj = 0; jj < 4; jj++) {
                    const float av = (&a4.x)[jj];
                    unsigned long long a2 = pk2(av);
                    ulonglong2 v2 = *(const ulonglong2*)(sv  + (j0+jj)*RSTR + d);
                    ulonglong2 b2 = *(const ulonglong2*)(skb + (j0+jj)*RSTR + d);
                    fma2(au01, a2, v2.x); fma2(au23, a2, v2.y);
                    fma2(aw01, a2, b2.x); fma2(aw23, a2, b2.y);
                }
            }
            float2 l, h;
            l = up2(au01); h = up2(au23);
            *(float4*)(g_u + base + i*D + d) = make_float4(l.x, l.y, h.x, h.y);
            l = up2(aw01); h = up2(aw23);
            *(float4*)(g_w + base + i*D + d) = make_float4(l.x, l.y, h.x, h.y);
        }
    }
}

// ---------------------------------------------------------------------------
// Scan kernel: R16 structure; q read RAW (scaled by g_qr in combine);
// q@S result carried in registers across the barrier (sPQ eliminated).
// ---------------------------------------------------------------------------
// tile buffer offsets (floats): q | kT(128x36) | w | u0 | attn | qr
#define OQ  0
#define OKT (C * RSTR)                       // 4224
#define OW  (OKT + D * KTSTR)                // 8832
#define OU0 (OW + C * RSTR)                  // 13056
#define OAT (OU0 + C * ASTR)                 // 14208
#define OQR (OAT + C * ASTR)                 // 15360
#define SBUF (OQR + 32)                      // 15392
#define PMAT (C * ASTR)                      // one 32x32 partial matrix

__device__ __forceinline__ void prefetch_chunk(
    uint32_t smb, int ci, int w, int lid, int t, int c, int v4, int v0,
    const float* gq, const float* gkT, const float* gw,
    const float* gu, const float* ga, const float* gqr)
{
    const size_t cb = (size_t)ci * (C * D);
    #pragma unroll
    for (int rr = 0; rr < 4; rr++) {
        const int r = w * 4 + rr;
        const uint32_t off = (uint32_t)(r * RSTR + lid * 4) * 4u;
        cpa16(smb + (uint32_t)OQ * 4u + off, gq + cb + r * D + lid * 4);
        cpa16(smb + (uint32_t)OW * 4u + off, gw + cb + r * D + lid * 4);
    }
    #pragma unroll
    for (int i = 0; i < 4; i++) {
        const int idx = t + 256 * i;
        const int row = idx >> 3;            // 0..127
        const int c4  = (idx & 7) * 4;
        cpa16(smb + (uint32_t)(OKT + row * KTSTR + c4) * 4u,
              gkT + cb + row * C + c4);
    }
    cpa16(smb + (uint32_t)(OU0 + c * ASTR + v4) * 4u, gu + cb + c * D + v0 + v4);
    cpa16(smb + (uint32_t)(OAT + c * ASTR + v4) * 4u,
          ga + (size_t)ci * (C * C) + c * C + v4);
    if (t < 8)
        cpa16(smb + (uint32_t)(OQR + t * 4) * 4u, gqr + (size_t)ci * C + t * 4);
    asm volatile("cp.async.commit_group;");
}

__global__ void __launch_bounds__(256, 1) scan_kernel(
    const float* __restrict__ q, float* __restrict__ out)
{
    extern __shared__ float s[];
    float* sS  = s;                         // 128 x VSLICE
    float* sb0 = sS + D * VSLICE;
    float* sb1 = sb0 + SBUF;
    float* sui = sb1 + SBUF;                // 32 x ASTR
    float* sPP = sui + C * ASTR;            // 8 x PMAT partial matrices (4 U, 4 Q)

    const int bh  = blockIdx.y;
    const int v0  = blockIdx.x * VSLICE;
    const int t   = threadIdx.x;
    const int w   = t >> 5;
    const int lid = t & 31;
    const int v4  = (t & 7) * 4;
    const int r0  = ((t >> 3) & 7) * 4;     // rows r0..r0+3
    const int dq  = t >> 6;                 // d quarter 0..3
    const int c   = t >> 3;

    #pragma unroll
    for (int rr = 0; rr < 4; rr++)
        *(float4*)(sS + (rr * 256 + t) * 4) = make_float4(0.f, 0.f, 0.f, 0.f);

    const uint32_t smb0 = (uint32_t)__cvta_generic_to_shared(sb0);
    const uint32_t smb1 = (uint32_t)__cvta_generic_to_shared(sb1);

    const size_t bhb = (size_t)bh * LSEQ * D;
    const float* gq  = q + bhb;             // RAW q (normalized on the fly)
    const float* gkT = g_kn + bhb;
    const float* gw  = g_w  + bhb;
    const float* gu  = g_u  + bhb;
    const float* ga  = g_attn + (size_t)bh * NCHUNK * (C * C);
    const float* gqr = g_qr + (size_t)bh * NCHUNK * C;

    prefetch_chunk(smb0, 0, w, lid, t, c, v4, v0, gq, gkT, gw, gu, ga, gqr);

    // persistent S accumulators: thread owns rows {c,c+32,c+64,c+96} x v4..v4+3
    unsigned long long SR0=0,SR1=0,SR2=0,SR3=0,SR4=0,SR5=0,SR6=0,SR7=0;

    for (int ci = 0; ci < NCHUNK; ci++) {
        float* B = (ci & 1) ? sb1 : sb0;
        const uint32_t smn = (ci & 1) ? smb0 : smb1;
        const float* sq  = B + OQ;
        const float* skT = B + OKT;
        const float* sw  = B + OW;
        const float* su0 = B + OU0;
        const float* sat = B + OAT;
        const float* sqr = B + OQR;

        asm volatile("cp.async.wait_group 0;");
        __syncthreads();                    // tiles ready + prev S update done

        const int cn = (ci + 1 < NCHUNK) ? ci + 1 : ci;
        prefetch_chunk(smn, cn, w, lid, t, c, v4, v0, gq, gkT, gw, gu, ga, gqr);

        // ---- phase 2: quarter-d GEMV, 4 rows/thread; ALL quarters store ----
        {
            unsigned long long aU[4][2], aQ[4][2];
            #pragma unroll
            for (int r = 0; r < 4; r++) {
                aU[r][0]=0; aU[r][1]=0; aQ[r][0]=0; aQ[r][1]=0;
            }
            const int dbeg = dq * 32;
            const float* wp = sw + dbeg;
            const float* qp = sq + dbeg;
            const float* Sp = sS + dbeg * VSLICE + v4;
            #pragma unroll 2
            for (int dg = 0; dg < 32; dg += 4) {
                float4 wv[4], qv[4];
                #pragma unroll
                for (int r = 0; r < 4; r++) {
                    wv[r] = *(const float4*)(wp + (r0 + r) * RSTR + dg);
                    qv[r] = *(const float4*)(qp + (r0 + r) * RSTR + dg);
                }
                #pragma unroll
                for (int i = 0; i < 4; i++) {
                    ulonglong2 S2 = *(const ulonglong2*)(Sp + (dg + i) * VSLICE);
                    #pragma unroll
                    for (int r = 0; r < 4; r++) {
                        unsigned long long w2 = pk2((&wv[r].x)[i]);
                        unsigned long long q2 = pk2((&qv[r].x)[i]);
                        fma2(aU[r][0], w2, S2.x); fma2(aU[r][1], w2, S2.y);
                        fma2(aQ[r][0], q2, S2.x); fma2(aQ[r][1], q2, S2.y);
                    }
                }
            }
            float* PU = sPP + dq * PMAT;
            float* PQ = sPP + (4 + dq) * PMAT;
            #pragma unroll
            for (int r = 0; r < 4; r++) {
                float2 l, h;
                l = up2(aU[r][0]); h = up2(aU[r][1]);
                *(float4*)(PU + (r0 + r) * ASTR + v4) = make_float4(l.x, l.y, h.x, h.y);
                l = up2(aQ[r][0]); h = up2(aQ[r][1]);
                *(float4*)(PQ + (r0 + r) * ASTR + v4) = make_float4(l.x, l.y, h.x, h.y);
            }
        }
        __syncthreads();

        // ---- combine: u_i to smem; q@S (scaled by qr) kept in REGISTERS ----
        unsigned long long o01, o23;
        {
            float4 u0 = *(const float4*)(su0 + c * ASTR + v4);
            float4 aU = make_float4(0.f,0.f,0.f,0.f);
            float4 aQ = make_float4(0.f,0.f,0.f,0.f);
            #pragma unroll
            for (int p = 0; p < 4; p++) {
                float4 pu = *(const float4*)(sPP + p * PMAT + c * ASTR + v4);
                float4 pq = *(const float4*)(sPP + (4+p) * PMAT + c * ASTR + v4);
                aU.x += pu.x; aU.y += pu.y; aU.z += pu.z; aU.w += pu.w;
                aQ.x += pq.x; aQ.y += pq.y; aQ.z += pq.z; aQ.w += pq.w;
            }
            *(float4*)(sui + c * ASTR + v4) = make_float4(
                u0.x - aU.x, u0.y - aU.y, u0.z - aU.z, u0.w - aU.w);
            const float qrv = sqr[c];
            o01 = pkf(aQ.x * qrv, aQ.y * qrv);
            o23 = pkf(aQ.z * qrv, aQ.w * qrv);
        }
        __syncthreads();

        // ---- fused phase 3+4: one e-loop; out + persistent S accumulate ----
        {
            #pragma unroll 2
            for (int e4 = 0; e4 < C; e4 += 4) {
                float4 kv0 = *(const float4*)(skT + (c      ) * KTSTR + e4);
                float4 kv1 = *(const float4*)(skT + (c +  32) * KTSTR + e4);
                float4 kv2 = *(const float4*)(skT + (c +  64) * KTSTR + e4);
                float4 kv3 = *(const float4*)(skT + (c +  96) * KTSTR + e4);
                float4 av4 = *(const float4*)(sat + c * ASTR + e4);
                #pragma unroll
                for (int ee = 0; ee < 4; ee++) {
                    const int e = e4 + ee;
                    ulonglong2 u2 = *(const ulonglong2*)(sui + e * ASTR + v4);
                    unsigned long long a2 = pk2((&av4.x)[ee]);
                    fma2(o01, a2, u2.x); fma2(o23, a2, u2.y);
                    unsigned long long k0 = pk2((&kv0.x)[ee]);
                    unsigned long long k1 = pk2((&kv1.x)[ee]);
                    unsigned long long k2 = pk2((&kv2.x)[ee]);
                    unsigned long long k3 = pk2((&kv3.x)[ee]);
                    fma2(SR0, k0, u2.x); fma2(SR1, k0, u2.y);
                    fma2(SR2, k1, u2.x); fma2(SR3, k1, u2.y);
                    fma2(SR4, k2, u2.x); fma2(SR5, k2, u2.y);
                    fma2(SR6, k3, u2.x); fma2(SR7, k3, u2.y);
                }
            }
            // write cumulative S to smem (no read needed)
            float2 l, h;
            l = up2(SR0); h = up2(SR1);
            *(float4*)(sS + (c      ) * VSLICE + v4) = make_float4(l.x, l.y, h.x, h.y);
            l = up2(SR2); h = up2(SR3);
            *(float4*)(sS + (c +  32) * VSLICE + v4) = make_float4(l.x, l.y, h.x, h.y);
            l = up2(SR4); h = up2(SR5);
            *(float4*)(sS + (c +  64) * VSLICE + v4) = make_float4(l.x, l.y, h.x, h.y);
            l = up2(SR6); h = up2(SR7);
            *(float4*)(sS + (c +  96) * VSLICE + v4) = make_float4(l.x, l.y, h.x, h.y);
            {
                float2 lo = up2(o01), hi = up2(o23);
                *(float4*)(out + bhb + (size_t)ci * (C * D) + c * D + v0 + v4) =
                    make_float4(lo.x, lo.y, hi.x, hi.y);
            }
        }
    }
}

// ---------------------------------------------------------------------------
extern "C" void kernel_launch(void* const* d_in, const int* in_sizes, int n_in,
                              void* d_out, int out_size)
{
    const float* q    = (const float*)d_in[0];
    const float* k    = (const float*)d_in[1];
    const float* v    = (const float*)d_in[2];
    const float* beta = (const float*)d_in[3];
    float* out = (float*)d_out;

    const size_t smemA = (size_t)(3 * C * RSTR + C * 128 + C * ASTR + 16 * 17)
                         * sizeof(float);
    const size_t smemB = (size_t)(D * VSLICE + 2 * SBUF + C * ASTR + 8 * PMAT)
                         * sizeof(float);

    cudaFuncSetAttribute(prep_kernel, cudaFuncAttributeMaxDynamicSharedMemorySize,
                         (int)smemA);
    cudaFuncSetAttribute(scan_kernel, cudaFuncAttributeMaxDynamicSharedMemorySize,
                         (int)smemB);

    prep_kernel<<<NC_TOTAL, 256, smemA>>>(q, k, v, beta);
    scan_kernel<<<dim3(NSPLIT, BH), 256, smemB>>>(q, out);
}